// round 14
// baseline (speedup 1.0000x reference)
#include <cuda_runtime.h>
#include <cuda_fp16.h>
#include <math.h>
#include <stdint.h>

#define BATCH 4096
#define TT    15
#define EMBD  300
#define HID   512
#define G3    1536
#define DD    1024
#define BT    (BATCH*TT)
#define VOCAB 12000
#define BH    (BATCH*HID)
#define VROWS 12032            // VOCAB padded to 128

#define KROW  20               // u32 per 32-k row chunk (16 fp16x2 + 4 pad)

// git GEMM: A(128)+B(128) rows/stage, 3 stages
#define GP_STAGE (256*KROW)
#define GP_SMEM  (3*GP_STAGE*4)     // 61440 B
// recurrence: A(64)+B(192) rows/stage, 4 stages (1 barrier/iter)
#define RC_STAGE (256*KROW)
#define RC_SMEM  (4*RC_STAGE*4)     // 81920 B (2 CTAs/SM fit)
// gw: A(128)+B(128), 2 stages
#define GW_STAGE (256*KROW)
#define GW_SMEM  (2*GW_STAGE*4)     // 40960 B
// attn: A(128)+B(256) rows/stage, 4 stages (1 barrier/iter)
#define AT_STAGE (384*KROW)
#define AT_SMEM  (4*AT_STAGE*4)     // 122880 B

// prep_all segment sizes (u32 elements)
#define S_EMB  (10*VROWS*16)
#define S_WIH  (10*G3*16)
#define S_WHH  (16*G3*16)
#define S_WD   (32*DD*16)
#define S_HTF  (2*2*BATCH*256)
#define S_TOTAL (S_EMB + 2*S_WIH + 2*S_WHH + 2*S_WD + S_HTF)

// ---------------- scratch -----------------------------------------------------
__device__ float    g_git_f[(size_t)VOCAB * G3];
__device__ float    g_git_b[(size_t)VOCAB * G3];
__device__ uint32_t g_embt[(size_t)S_EMB];
__device__ uint32_t g_wiht[(size_t)2 * S_WIH];
__device__ uint32_t g_whht[(size_t)2 * S_WHH];
__device__ uint32_t g_wlt [(size_t)S_WD];
__device__ uint32_t g_wgt [(size_t)S_WD];
__device__ uint32_t g_htf [(size_t)S_HTF];
__device__ float    g_yword[(size_t)BT * DD];
__device__ uint32_t g_ywh [(size_t)32 * BT * 16];      // fp16x2 permuted y (attn A)
__device__ float    g_ypool[BATCH * DD];
__device__ float    g_gw  [BATCH * DD];
__device__ float    g_wraw[BT];

// ---------------- helpers ------------------------------------------------------
__device__ __forceinline__ uint32_t pkh2(float lo, float hi) {
    __half2 h = __floats2half2_rn(lo, hi);
    return *(uint32_t*)&h;
}
__device__ __forceinline__ void mma16(float* c,
    uint32_t a0, uint32_t a1, uint32_t a2, uint32_t a3,
    uint32_t b0, uint32_t b1)
{
    asm volatile(
        "mma.sync.aligned.m16n8k16.row.col.f32.f16.f16.f32 "
        "{%0,%1,%2,%3},{%4,%5,%6,%7},{%8,%9},{%0,%1,%2,%3};"
        : "+f"(c[0]), "+f"(c[1]), "+f"(c[2]), "+f"(c[3])
        : "r"(a0), "r"(a1), "r"(a2), "r"(a3), "r"(b0), "r"(b1));
}
__device__ __forceinline__ float sigm(float x) { return 1.f / (1.f + expf(-x)); }
__device__ __forceinline__ void cp16(uint32_t saddr, const void* g) {
    asm volatile("cp.async.cg.shared.global [%0], [%1], 16;" :: "r"(saddr), "l"(g));
}

// 2 m16-tiles x NT n8-tiles for one k32 chunk (fragments pre-permuted in smem)
template<int NT>
__device__ __forceinline__ void mm16t(const uint32_t* As, const uint32_t* Bs,
    int wm0, int wn0, int g, int q, float c[][NT][4])
{
    const uint4* A4 = (const uint4*)As;   // row stride 5 uint4
    const uint4* B4 = (const uint4*)Bs;
    uint4 aL[2], aH[2], bu[NT];
    aL[0] = A4[(wm0 + g     ) * 5 + q];
    aH[0] = A4[(wm0 + g +  8) * 5 + q];
    aL[1] = A4[(wm0 + g + 16) * 5 + q];
    aH[1] = A4[(wm0 + g + 24) * 5 + q];
    #pragma unroll
    for (int nt = 0; nt < NT; nt++) bu[nt] = B4[(wn0 + nt * 8 + g) * 5 + q];
    #pragma unroll
    for (int mt = 0; mt < 2; mt++)
        #pragma unroll
        for (int nt = 0; nt < NT; nt++)
            mma16(c[mt][nt], aL[mt].x, aH[mt].x, aL[mt].y, aH[mt].y,
                  bu[nt].x, bu[nt].y);
    #pragma unroll
    for (int mt = 0; mt < 2; mt++)
        #pragma unroll
        for (int nt = 0; nt < NT; nt++)
            mma16(c[mt][nt], aL[mt].z, aH[mt].z, aL[mt].w, aH[mt].w,
                  bu[nt].z, bu[nt].w);
}

// ---------------- merged one-time prep (all weight converts + h zero) ----------
__device__ __forceinline__ void conv_one(
    const float* __restrict__ in, uint32_t* __restrict__ out,
    int idx, int R, int Rout, int K)
{
    const int kc  = idx / (Rout * 16);
    const int rem = idx % (Rout * 16);
    const int r = rem >> 4, slot = rem & 15;
    const int kp = (slot & 3) * 4 + (slot >> 2);
    const int k0 = kc * 32 + kp * 2;
    const float v0 = (r < R && k0     < K) ? in[(size_t)r * K + k0]     : 0.f;
    const float v1 = (r < R && k0 + 1 < K) ? in[(size_t)r * K + k0 + 1] : 0.f;
    out[idx] = pkh2(v0, v1);
}

__global__ void prep_all(
    const float* __restrict__ emb,
    const float* __restrict__ wihf, const float* __restrict__ wihb,
    const float* __restrict__ whhf, const float* __restrict__ whhb,
    const float* __restrict__ wl,   const float* __restrict__ wg,
    uint32_t* __restrict__ embt, uint32_t* __restrict__ wiht,
    uint32_t* __restrict__ whht, uint32_t* __restrict__ wlt,
    uint32_t* __restrict__ wgt,  uint32_t* __restrict__ htf)
{
    int idx = blockIdx.x * 256 + threadIdx.x;
    if (idx < S_EMB) { conv_one(emb, embt, idx, VOCAB, VROWS, EMBD); return; }
    idx -= S_EMB;
    if (idx < S_WIH) { conv_one(wihf, wiht, idx, G3, G3, EMBD); return; }
    idx -= S_WIH;
    if (idx < S_WIH) { conv_one(wihb, wiht + S_WIH, idx, G3, G3, EMBD); return; }
    idx -= S_WIH;
    if (idx < S_WHH) { conv_one(whhf, whht, idx, G3, G3, HID); return; }
    idx -= S_WHH;
    if (idx < S_WHH) { conv_one(whhb, whht + S_WHH, idx, G3, G3, HID); return; }
    idx -= S_WHH;
    if (idx < S_WD)  { conv_one(wl, wlt, idx, DD, DD, DD); return; }
    idx -= S_WD;
    if (idx < S_WD)  { conv_one(wg, wgt, idx, DD, DD, DD); return; }
    idx -= S_WD;
    if (idx < S_HTF) htf[idx] = 0u;
}

// ---------------- y fp32 -> fp16x2 permuted convert (for attn A) ---------------
__global__ void ywconv(const float* __restrict__ yw, uint32_t* __restrict__ ywh)
{
    const int u = blockIdx.x * 256 + threadIdx.x;   // 32*BT*4 uint4 units
    if (u >= 32 * BT * 4) return;
    const int kc  = u / (BT * 4);
    const int rem = u % (BT * 4);
    const int r = rem >> 2, j = rem & 3;
    const float* p = yw + (size_t)r * DD + kc * 32 + 2 * j;
    const float2 f0 = *(const float2*)(p);
    const float2 f1 = *(const float2*)(p + 8);
    const float2 f2 = *(const float2*)(p + 16);
    const float2 f3 = *(const float2*)(p + 24);
    uint4 w;
    w.x = pkh2(f0.x, f0.y); w.y = pkh2(f1.x, f1.y);
    w.z = pkh2(f2.x, f2.y); w.w = pkh2(f3.x, f3.y);
    *(uint4*)&ywh[((size_t)kc * BT + r) * 16 + j * 4] = w;
}

// ================= git GEMM: prepped x prepped, 3-stage cp.async ===============
__global__ void __launch_bounds__(256) hgemm_pp(
    const uint32_t* __restrict__ At,
    const uint32_t* __restrict__ Wt, const uint32_t* __restrict__ Wt2,
    const float* __restrict__ bias, const float* __restrict__ bias2,
    float* __restrict__ C, float* __restrict__ C2,
    int Mout, int Ar, int N, int KC)
{
    const uint32_t* W = Wt; const float* bi = bias; float* Co = C;
    if (blockIdx.z == 1) { W = Wt2; bi = bias2; Co = C2; }
    extern __shared__ uint32_t sm[];
    const uint32_t sbase = (uint32_t)__cvta_generic_to_shared(sm);

    const int tid  = threadIdx.x;
    const int lane = tid & 31, wid = tid >> 5;
    const int g = lane >> 2, q = lane & 3;
    const int wm0 = (wid & 3) * 32;
    const int wn0 = (wid >> 2) * 64;
    const int row0 = blockIdx.x * 128;
    const int col0 = blockIdx.y * 128;

    auto issue = [&](int kc, int st) {
        const uint32_t s0 = sbase + st * GP_STAGE * 4;
        #pragma unroll
        for (int s = 0; s < 2; s++) {
            const int u = tid + s * 256;
            const int r = u >> 2, j = u & 3;
            cp16(s0 + (r * KROW + j * 4) * 4,
                 At + ((size_t)kc * Ar + row0 + r) * 16 + j * 4);
        }
        #pragma unroll
        for (int s = 0; s < 2; s++) {
            const int u = tid + s * 256;
            const int r = u >> 2, j = u & 3;
            cp16(s0 + (128 * KROW + r * KROW + j * 4) * 4,
                 W + ((size_t)kc * N + col0 + r) * 16 + j * 4);
        }
        asm volatile("cp.async.commit_group;");
    };

    float c[2][8][4];
    #pragma unroll
    for (int mt = 0; mt < 2; mt++)
        #pragma unroll
        for (int nt = 0; nt < 8; nt++)
            #pragma unroll
            for (int j = 0; j < 4; j++) c[mt][nt][j] = 0.f;

    issue(0, 0);
    if (KC > 1) issue(1, 1);
    for (int it = 0; it < KC; it++) {
        if (it + 1 < KC) asm volatile("cp.async.wait_group 1;");
        else             asm volatile("cp.async.wait_group 0;");
        __syncthreads();
        if (it + 2 < KC) issue(it + 2, (it + 2) % 3);
        const uint32_t* curS = sm + (it % 3) * GP_STAGE;
        mm16t<8>(curS, curS + 128 * KROW, wm0, wn0, g, q, c);
        __syncthreads();
    }

    #pragma unroll
    for (int mt = 0; mt < 2; mt++) {
        const int r = row0 + wm0 + mt * 16 + g;
        #pragma unroll
        for (int nt = 0; nt < 8; nt++) {
            const int n = col0 + wn0 + nt * 8 + q * 2;
            const float b0 = bi[n], b1 = bi[n + 1];
            if (r < Mout)
                *(float2*)(Co + (size_t)r * N + n) =
                    make_float2(c[mt][nt][0] + b0, c[mt][nt][1] + b1);
            if (r + 8 < Mout)
                *(float2*)(Co + (size_t)(r + 8) * N + n) =
                    make_float2(c[mt][nt][2] + b0, c[mt][nt][3] + b1);
        }
    }
}

// ================= fused GRU recurrence (fp16, 4-stage, 1 barrier/iter) ========
__global__ void __launch_bounds__(256, 2) rec_step(
    const int* __restrict__ inds,
    const float* __restrict__ git_f, const float* __restrict__ git_b,
    const uint32_t* __restrict__ whht,
    const float* __restrict__ bhh_f, const float* __restrict__ bhh_b,
    uint32_t* __restrict__ htf,
    float* __restrict__ y_word, int t)
{
    const int dir = blockIdx.z;
    const int cur = t & 1, nxt = cur ^ 1;
    const float* git = dir ? git_b : git_f;
    const float* bhh = dir ? bhh_b : bhh_f;
    const int tt  = dir ? (TT - 1 - t) : t;
    const int off = dir ? HID : 0;
    const uint32_t* Wp    = whht + (size_t)dir * S_WHH;
    const uint32_t* hprev = htf + ((size_t)dir * 2 + cur) * BATCH * 256;
    uint32_t*       hnext = htf + ((size_t)dir * 2 + nxt) * BATCH * 256;

    extern __shared__ uint32_t sm[];
    const uint32_t sbase = (uint32_t)__cvta_generic_to_shared(sm);

    const int tid  = threadIdx.x;
    const int lane = tid & 31, wid = tid >> 5;
    const int g = lane >> 2, q = lane & 3;
    const int wm0 = (wid & 1) * 32;       // 2 m-warps
    const int wn0 = (wid >> 1) * 16;      // 4 n-warps (16 hid cols each)
    const int row0 = blockIdx.x * 64;
    const int col0 = blockIdx.y * 64;

    auto issue = [&](int kc, int st) {
        const uint32_t s0 = sbase + st * RC_STAGE * 4;
        {   // A: 64 rows x 4 units = 256
            const int r = tid >> 2, j = tid & 3;
            cp16(s0 + (r * KROW + j * 4) * 4,
                 hprev + (size_t)(row0 + r) * 256 + kc * 16 + j * 4);
        }
        #pragma unroll
        for (int s = 0; s < 3; s++) {     // B: 192 rows x 4 units = 768
            const int u = tid + s * 256;
            const int r = u >> 2, j = u & 3;
            const int gate = r >> 6, wi = r & 63;
            cp16(s0 + (64 * KROW + r * KROW + j * 4) * 4,
                 Wp + ((size_t)kc * G3 + gate * HID + col0 + wi) * 16 + j * 4);
        }
        asm volatile("cp.async.commit_group;");
    };

    float c[3][2][2][4];
    #pragma unroll
    for (int gt = 0; gt < 3; gt++)
        #pragma unroll
        for (int mt = 0; mt < 2; mt++)
            #pragma unroll
            for (int nt = 0; nt < 2; nt++)
                #pragma unroll
                for (int j = 0; j < 4; j++) c[gt][mt][nt][j] = 0.f;

    const int nk = HID / 32;  // 16
    issue(0, 0);
    issue(1, 1);

    for (int it = 0; it < nk; it++) {
        if (it + 1 < nk) asm volatile("cp.async.wait_group 1;");
        else             asm volatile("cp.async.wait_group 0;");
        __syncthreads();
        if (it + 2 < nk) issue(it + 2, (it + 2) & 3);

        const uint32_t* curS = sm + (it & 3) * RC_STAGE;
        const uint4* A4 = (const uint4*)curS;
        const uint4* B4 = (const uint4*)(curS + 64 * KROW);
        const uint4 aL0 = A4[(wm0 + g     ) * 5 + q];
        const uint4 aH0 = A4[(wm0 + g +  8) * 5 + q];
        const uint4 aL1 = A4[(wm0 + g + 16) * 5 + q];
        const uint4 aH1 = A4[(wm0 + g + 24) * 5 + q];
        uint4 bu[3][2];
        #pragma unroll
        for (int gt = 0; gt < 3; gt++)
            #pragma unroll
            for (int nt = 0; nt < 2; nt++)
                bu[gt][nt] = B4[(gt * 64 + wn0 + nt * 8 + g) * 5 + q];
        #pragma unroll
        for (int gt = 0; gt < 3; gt++)
            #pragma unroll
            for (int nt = 0; nt < 2; nt++) {
                mma16(c[gt][0][nt], aL0.x, aH0.x, aL0.y, aH0.y,
                      bu[gt][nt].x, bu[gt][nt].y);
                mma16(c[gt][1][nt], aL1.x, aH1.x, aL1.y, aH1.y,
                      bu[gt][nt].x, bu[gt][nt].y);
            }
        #pragma unroll
        for (int gt = 0; gt < 3; gt++)
            #pragma unroll
            for (int nt = 0; nt < 2; nt++) {
                mma16(c[gt][0][nt], aL0.z, aH0.z, aL0.w, aH0.w,
                      bu[gt][nt].z, bu[gt][nt].w);
                mma16(c[gt][1][nt], aL1.z, aH1.z, aL1.w, aH1.w,
                      bu[gt][nt].z, bu[gt][nt].w);
            }
    }

    // ---- GRU cell epilogue ----
    #pragma unroll
    for (int mt = 0; mt < 2; mt++) {
        #pragma unroll
        for (int rr = 0; rr < 2; rr++) {
            const int b = row0 + wm0 + mt * 16 + g + rr * 8;
            const int tok = inds[b * TT + tt];
            const float* gib = git + (size_t)tok * G3;
            #pragma unroll
            for (int nt = 0; nt < 2; nt++) {
                const int hg = col0 + wn0 + nt * 8 + q * 2;   // even
                const int j0 = rr * 2;
                const int kpair = (hg & 31) >> 1;
                const int slot = (kpair & 3) * 4 + (kpair >> 2);
                const size_t hw = (size_t)b * 256 + (hg >> 5) * 16 + slot;
                const __half2 hp2 = *(const __half2*)&hprev[hw];
                float hn2[2];
                #pragma unroll
                for (int e = 0; e < 2; e++) {
                    const int hh = hg + e;
                    const float gir = gib[hh];
                    const float giz = gib[HID + hh];
                    const float gin = gib[2 * HID + hh];
                    const float ghr = c[0][mt][nt][j0 + e] + bhh[hh];
                    const float ghz = c[1][mt][nt][j0 + e] + bhh[HID + hh];
                    const float ghn = c[2][mt][nt][j0 + e] + bhh[2 * HID + hh];
                    const float hp = (e == 0) ? __low2float(hp2) : __high2float(hp2);
                    const float r = sigm(gir + ghr);
                    const float z = sigm(giz + ghz);
                    const float n = tanhf(gin + r * ghn);
                    hn2[e] = (1.f - z) * n + z * hp;
                }
                hnext[hw] = pkh2(hn2[0], hn2[1]);
                *(float2*)(y_word + (size_t)(b * TT + tt) * DD + off + hg) =
                    make_float2(hn2[0], hn2[1]);
            }
        }
    }
}

// ================= gw GEMM: fp32-A convert x prepped-B =========================
__global__ void __launch_bounds__(256) hgemm_gw(
    const float* __restrict__ A, const uint32_t* __restrict__ Wt,
    const float* __restrict__ bias, const float* __restrict__ wc,
    float* __restrict__ C)
{
    extern __shared__ uint32_t sm[];
    const int tid  = threadIdx.x;
    const int lane = tid & 31, wid = tid >> 5;
    const int g = lane >> 2, q = lane & 3;
    const int wm0 = (wid & 3) * 32;
    const int wn0 = (wid >> 2) * 64;
    const int row0 = blockIdx.x * 128;
    const int col0 = blockIdx.y * 128;
    const int sr = tid >> 1;
    const int j0s = (tid & 1) * 2;

    const float* arow = A + (size_t)(row0 + sr) * DD;

    auto stageA = [&](uint32_t* sa, int kc) {
        #pragma unroll
        for (int jj = 0; jj < 2; jj++) {
            const int j = j0s + jj;
            const float* p = arow + kc * 32 + 2 * j;
            const float2 f0 = *(const float2*)(p);
            const float2 f1 = *(const float2*)(p + 8);
            const float2 f2 = *(const float2*)(p + 16);
            const float2 f3 = *(const float2*)(p + 24);
            uint4 w;
            w.x = pkh2(f0.x, f0.y); w.y = pkh2(f1.x, f1.y);
            w.z = pkh2(f2.x, f2.y); w.w = pkh2(f3.x, f3.y);
            *(uint4*)&sa[sr * KROW + j * 4] = w;
        }
    };
    auto stageB = [&](uint32_t* sb, const uint4* rbu) {
        #pragma unroll
        for (int jj = 0; jj < 2; jj++)
            *(uint4*)&sb[sr * KROW + (j0s + jj) * 4] = rbu[jj];
    };
    auto loadB = [&](uint4* rbu, int kc) {
        #pragma unroll
        for (int jj = 0; jj < 2; jj++)
            rbu[jj] = *(const uint4*)(Wt + ((size_t)kc * DD + col0 + sr) * 16
                                          + (j0s + jj) * 4);
    };

    float c[2][8][4];
    #pragma unroll
    for (int mt = 0; mt < 2; mt++)
        #pragma unroll
        for (int nt = 0; nt < 8; nt++)
            #pragma unroll
            for (int j = 0; j < 4; j++) c[mt][nt][j] = 0.f;

    const int nk = DD / 32;
    uint4 rbu[2];
    loadB(rbu, 0);
    stageA(sm, 0);
    stageB(sm + 128 * KROW, rbu);
    __syncthreads();

    for (int it = 0; it < nk; it++) {
        const bool more = (it + 1 < nk);
        if (more) loadB(rbu, it + 1);
        const uint32_t* curS = sm + (it & 1) * GW_STAGE;
        mm16t<8>(curS, curS + 128 * KROW, wm0, wn0, g, q, c);
        if (more) {
            uint32_t* nx = sm + ((it + 1) & 1) * GW_STAGE;
            stageA(nx, it + 1);
            stageB(nx + 128 * KROW, rbu);
            __syncthreads();
        }
    }

    #pragma unroll
    for (int mt = 0; mt < 2; mt++) {
        const int r = row0 + wm0 + mt * 16 + g;
        #pragma unroll
        for (int nt = 0; nt < 8; nt++) {
            const int n = col0 + wn0 + nt * 8 + q * 2;
            const float b0 = bias[n], b1 = bias[n + 1];
            const float w0 = wc[n], w1 = wc[n + 1];
            *(float2*)(C + (size_t)r * DD + n) =
                make_float2(tanhf(c[mt][nt][0] + b0) * w0,
                            tanhf(c[mt][nt][1] + b1) * w1);
            *(float2*)(C + (size_t)(r + 8) * DD + n) =
                make_float2(tanhf(c[mt][nt][2] + b0) * w0,
                            tanhf(c[mt][nt][3] + b1) * w1);
        }
    }
}

// ========== fused attention logits: 512t, 4-stage, 1 barrier/iter ==============
__global__ void __launch_bounds__(512) attn_w(
    const uint32_t* __restrict__ ywh, const uint32_t* __restrict__ wlt,
    const float* __restrict__ bl, const float* __restrict__ gw,
    const float* __restrict__ bc, float* __restrict__ wraw)
{
    extern __shared__ uint32_t sm[];
    __shared__ float red[128][17];

    const int tid  = threadIdx.x;
    const int lane = tid & 31, wid = tid >> 5;       // 0..15
    const int g = lane >> 2, q = lane & 3;
    const int wm0 = (wid & 3) * 32;
    const int wn0 = (wid >> 2) * 64;
    const int row0 = blockIdx.x * 128;
    const uint32_t sbase = (uint32_t)__cvta_generic_to_shared(sm);

    auto issue = [&](int kc, int col0, int st) {
        const uint32_t s0 = sbase + st * AT_STAGE * 4;
        {   // A: 128 rows x 4 units = 512
            const int r = tid >> 2, j = tid & 3;
            cp16(s0 + (r * KROW + j * 4) * 4,
                 ywh + ((size_t)kc * BT + row0 + r) * 16 + j * 4);
        }
        {   // B: 256 rows x 4 units = 1024 (units tid, tid+512)
            const int r = tid >> 2, j = tid & 3;
            cp16(s0 + (128 * KROW + r * KROW + j * 4) * 4,
                 wlt + ((size_t)kc * DD + col0 + r) * 16 + j * 4);
            const int u = tid + 512;
            const int r2 = u >> 2, j2 = u & 3;
            cp16(s0 + (128 * KROW + r2 * KROW + j2 * 4) * 4,
                 wlt + ((size_t)kc * DD + col0 + r2) * 16 + j2 * 4);
        }
        asm volatile("cp.async.commit_group;");
    };

    int rbi0[2], rbi1[2];
    #pragma unroll
    for (int mt = 0; mt < 2; mt++) {
        const int r = row0 + wm0 + mt * 16 + g;
        rbi0[mt] = r / TT;
        rbi1[mt] = (r + 8) / TT;
    }
    float rowsum[2][2] = {{0.f, 0.f}, {0.f, 0.f}};

    const int nk = DD / 32;   // 32

    for (int ct = 0; ct < DD / 256; ct++) {
        const int col0 = ct * 256;

        float c[2][8][4];
        #pragma unroll
        for (int mt = 0; mt < 2; mt++)
            #pragma unroll
            for (int nt = 0; nt < 8; nt++)
                #pragma unroll
                for (int j = 0; j < 4; j++) c[mt][nt][j] = 0.f;

        issue(0, col0, 0);
        issue(1, col0, 1);

        for (int it = 0; it < nk; it++) {
            if (it + 1 < nk) asm volatile("cp.async.wait_group 1;");
            else             asm volatile("cp.async.wait_group 0;");
            __syncthreads();
            if (it + 2 < nk) issue(it + 2, col0, (it + 2) & 3);
            const uint32_t* curS = sm + (it & 3) * AT_STAGE;
            mm16t<8>(curS, curS + 128 * KROW, wm0, wn0, g, q, c);
        }

        #pragma unroll
        for (int mt = 0; mt < 2; mt++) {
            #pragma unroll
            for (int nt = 0; nt < 8; nt++) {
                const int n = col0 + wn0 + nt * 8 + q * 2;
                const float bb0 = bl[n], bb1 = bl[n + 1];
                rowsum[mt][0] += tanhf(c[mt][nt][0] + bb0) * gw[(size_t)rbi0[mt] * DD + n]
                               + tanhf(c[mt][nt][1] + bb1) * gw[(size_t)rbi0[mt] * DD + n + 1];
                rowsum[mt][1] += tanhf(c[mt][nt][2] + bb0) * gw[(size_t)rbi1[mt] * DD + n]
                               + tanhf(c[mt][nt][3] + bb1) * gw[(size_t)rbi1[mt] * DD + n + 1];
            }
        }
        __syncthreads();   // ring-reuse safety across column passes
    }

    const int rc = (wid >> 2) * 4 + q;   // 0..15
    #pragma unroll
    for (int mt = 0; mt < 2; mt++) {
        red[wm0 + mt * 16 + g    ][rc] = rowsum[mt][0];
        red[wm0 + mt * 16 + g + 8][rc] = rowsum[mt][1];
    }
    __syncthreads();
    if (tid < 128) {
        float s = 0.f;
        #pragma unroll
        for (int x = 0; x < 16; x++) s += red[tid][x];
        wraw[row0 + tid] = s + bc[0];
    }
}

// ---------------- small kernels ------------------------------------------------
__global__ void maxpool(const int* __restrict__ inds,
                        const float* __restrict__ y_word,
                        float* __restrict__ y_pool)
{
    const int idx = blockIdx.x * 256 + threadIdx.x;
    const int b = idx >> 10;
    const int d = idx & (DD - 1);
    float m = -INFINITY;
    #pragma unroll
    for (int t = 0; t < TT; t++) {
        if (inds[b * TT + t] != 0)
            m = fmaxf(m, y_word[(size_t)(b * TT + t) * DD + d]);
    }
    y_pool[idx] = m;
}

__global__ void softmax_out(const float* __restrict__ w_raw,
                            const float* __restrict__ y_word,
                            float* __restrict__ out)
{
    __shared__ float p[TT];
    const int b = blockIdx.x;
    if (threadIdx.x == 0) {
        float v[TT]; float mx = -INFINITY;
        #pragma unroll
        for (int t = 0; t < TT; t++) { v[t] = w_raw[b * TT + t]; mx = fmaxf(mx, v[t]); }
        float s = 0.f;
        #pragma unroll
        for (int t = 0; t < TT; t++) { v[t] = expf(v[t] - mx); s += v[t]; }
        const float inv = 1.f / s;
        #pragma unroll
        for (int t = 0; t < TT; t++) p[t] = v[t] * inv;
    }
    __syncthreads();
    for (int d = threadIdx.x; d < DD; d += 256) {
        float s = 0.f;
        #pragma unroll
        for (int t = 0; t < TT; t++)
            s += p[t] * y_word[((size_t)(b * TT + t)) * DD + d];
        out[(size_t)b * DD + d] = s;
    }
}

// ---------------- host launch --------------------------------------------------
extern "C" void kernel_launch(void* const* d_in, const int* in_sizes, int n_in,
                              void* d_out, int out_size)
{
    const int*   inds     = (const int*)  d_in[0];
    const float* emb      = (const float*)d_in[1];
    const float* w_ih_f   = (const float*)d_in[2];
    const float* w_hh_f   = (const float*)d_in[3];
    const float* b_ih_f   = (const float*)d_in[4];
    const float* b_hh_f   = (const float*)d_in[5];
    const float* w_ih_b   = (const float*)d_in[6];
    const float* w_hh_b   = (const float*)d_in[7];
    const float* b_ih_b   = (const float*)d_in[8];
    const float* b_hh_b   = (const float*)d_in[9];
    const float* w_local  = (const float*)d_in[10];
    const float* b_local  = (const float*)d_in[11];
    const float* w_global = (const float*)d_in[12];
    const float* b_global = (const float*)d_in[13];
    const float* w_common = (const float*)d_in[14];
    const float* b_common = (const float*)d_in[15];
    float* out = (float*)d_out;

    float *git_f, *git_b, *yw, *yp, *gw, *wraw;
    uint32_t *embt, *wiht, *whht, *wlt, *wgt, *htf, *ywh;
    cudaGetSymbolAddress((void**)&git_f, g_git_f);
    cudaGetSymbolAddress((void**)&git_b, g_git_b);
    cudaGetSymbolAddress((void**)&embt, g_embt);
    cudaGetSymbolAddress((void**)&wiht, g_wiht);
    cudaGetSymbolAddress((void**)&whht, g_whht);
    cudaGetSymbolAddress((void**)&wlt,  g_wlt);
    cudaGetSymbolAddress((void**)&wgt,  g_wgt);
    cudaGetSymbolAddress((void**)&htf,  g_htf);
    cudaGetSymbolAddress((void**)&yw,   g_yword);
    cudaGetSymbolAddress((void**)&ywh,  g_ywh);
    cudaGetSymbolAddress((void**)&yp,   g_ypool);
    cudaGetSymbolAddress((void**)&gw,   g_gw);
    cudaGetSymbolAddress((void**)&wraw, g_wraw);

    cudaFuncSetAttribute(hgemm_pp, cudaFuncAttributeMaxDynamicSharedMemorySize, GP_SMEM);
    cudaFuncSetAttribute(rec_step, cudaFuncAttributeMaxDynamicSharedMemorySize, RC_SMEM);
    cudaFuncSetAttribute(hgemm_gw, cudaFuncAttributeMaxDynamicSharedMemorySize, GW_SMEM);
    cudaFuncSetAttribute(attn_w,   cudaFuncAttributeMaxDynamicSharedMemorySize, AT_SMEM);

    // 0. merged one-time prep: all weight converts + h zero (single launch)
    prep_all<<<(S_TOTAL + 255) / 256, 256>>>(emb, w_ih_f, w_ih_b, w_hh_f, w_hh_b,
                                             w_local, w_global,
                                             embt, wiht, whht, wlt, wgt, htf);

    // 1. per-vocab gi table (incl. b_ih), both dirs
    dim3 gt_grid(VROWS / 128, G3 / 128, 2);
    hgemm_pp<<<gt_grid, 256, GP_SMEM>>>(embt, wiht, wiht + (size_t)S_WIH,
                                        b_ih_f, b_ih_b, git_f, git_b,
                                        VOCAB, VROWS, G3, 10);

    // 2. fused bidirectional GRU recurrence (64x64, 2 CTAs/SM, 4-stage ring)
    dim3 rec_grid(BATCH / 64, HID / 64, 2);
    for (int t = 0; t < TT; t++) {
        rec_step<<<rec_grid, 256, RC_SMEM>>>(inds, git_f, git_b, whht,
                                             b_hh_f, b_hh_b, htf, yw, t);
    }

    // 3. y fp32 -> fp16x2 permuted (attn A operand)
    ywconv<<<(32 * BT * 4 + 255) / 256, 256>>>(yw, ywh);

    // 4. masked max pool
    maxpool<<<(BATCH * DD) / 256, 256>>>(inds, yw, yp);

    // 5. gw = tanh(y_pool @ w_global^T + b_global) * w_common
    dim3 gw_grid(BATCH / 128, DD / 128, 1);
    hgemm_gw<<<gw_grid, 256, GW_SMEM>>>(yp, wgt, b_global, w_common, gw);

    // 6. fused l_emb -> tanh -> dot(gw) -> attention logits (all cp.async)
    attn_w<<<BT / 128, 512, AT_SMEM>>>(ywh, wlt, b_local, gw, b_common, wraw);

    // 7. softmax over T + weighted sum
    softmax_out<<<BATCH, 256>>>(wraw, yw, out);
}

// round 15
// speedup vs baseline: 1.0744x; 1.0744x over previous
#include <cuda_runtime.h>
#include <cuda_fp16.h>
#include <math.h>
#include <stdint.h>

#define BATCH 4096
#define TT    15
#define EMBD  300
#define HID   512
#define G3    1536
#define DD    1024
#define BT    (BATCH*TT)
#define VOCAB 12000
#define BH    (BATCH*HID)
#define VROWS 12032            // VOCAB padded to 128

#define KROW  20               // u32 per 32-k row chunk (16 fp16x2 + 4 pad)

// git GEMM: A(128)+B(128) rows/stage, 3 stages
#define GP_STAGE (256*KROW)
#define GP_SMEM  (3*GP_STAGE*4)     // 61440 B
// recurrence: A(64)+B(192) rows/stage, 3 stages
#define RC_STAGE (256*KROW)
#define RC_SMEM  (3*RC_STAGE*4)     // 61440 B
// gw: A(128)+B(128), 2 stages
#define GW_STAGE (256*KROW)
#define GW_SMEM  (2*GW_STAGE*4)     // 40960 B
// attn: A(128)+B(256) rows/stage, 3 stages (all cp.async)
#define AT_STAGE (384*KROW)
#define AT_SMEM  (3*AT_STAGE*4)     // 92160 B

// prep_all segment sizes (u32 elements)
#define S_EMB  (10*VROWS*16)
#define S_WIH  (10*G3*16)
#define S_WHH  (16*G3*16)
#define S_WD   (32*DD*16)
#define S_HTF  (2*2*BATCH*256)
#define S_TOTAL (S_EMB + 2*S_WIH + 2*S_WHH + 2*S_WD + S_HTF)

// ---------------- scratch -----------------------------------------------------
__device__ float    g_git_f[(size_t)VOCAB * G3];
__device__ float    g_git_b[(size_t)VOCAB * G3];
__device__ uint32_t g_embt[(size_t)S_EMB];
__device__ uint32_t g_wiht[(size_t)2 * S_WIH];
__device__ uint32_t g_whht[(size_t)2 * S_WHH];
__device__ uint32_t g_wlt [(size_t)S_WD];
__device__ uint32_t g_wgt [(size_t)S_WD];
__device__ uint32_t g_htf [(size_t)S_HTF];
__device__ float    g_yword[(size_t)BT * DD];
__device__ uint32_t g_ywh [(size_t)32 * BT * 16];      // fp16x2 permuted y (attn A)
__device__ float    g_ypool[BATCH * DD];
__device__ float    g_gw  [BATCH * DD];
__device__ float    g_wraw[BT];

// ---------------- helpers ------------------------------------------------------
__device__ __forceinline__ uint32_t pkh2(float lo, float hi) {
    __half2 h = __floats2half2_rn(lo, hi);
    return *(uint32_t*)&h;
}
__device__ __forceinline__ void mma16(float* c,
    uint32_t a0, uint32_t a1, uint32_t a2, uint32_t a3,
    uint32_t b0, uint32_t b1)
{
    asm volatile(
        "mma.sync.aligned.m16n8k16.row.col.f32.f16.f16.f32 "
        "{%0,%1,%2,%3},{%4,%5,%6,%7},{%8,%9},{%0,%1,%2,%3};"
        : "+f"(c[0]), "+f"(c[1]), "+f"(c[2]), "+f"(c[3])
        : "r"(a0), "r"(a1), "r"(a2), "r"(a3), "r"(b0), "r"(b1));
}
__device__ __forceinline__ float sigm(float x) { return 1.f / (1.f + expf(-x)); }
__device__ __forceinline__ void cp16(uint32_t saddr, const void* g) {
    asm volatile("cp.async.cg.shared.global [%0], [%1], 16;" :: "r"(saddr), "l"(g));
}

// 2 m16-tiles x NT n8-tiles for one k32 chunk (fragments pre-permuted in smem)
template<int NT>
__device__ __forceinline__ void mm16t(const uint32_t* As, const uint32_t* Bs,
    int wm0, int wn0, int g, int q, float c[][NT][4])
{
    const uint4* A4 = (const uint4*)As;   // row stride 5 uint4
    const uint4* B4 = (const uint4*)Bs;
    uint4 aL[2], aH[2], bu[NT];
    aL[0] = A4[(wm0 + g     ) * 5 + q];
    aH[0] = A4[(wm0 + g +  8) * 5 + q];
    aL[1] = A4[(wm0 + g + 16) * 5 + q];
    aH[1] = A4[(wm0 + g + 24) * 5 + q];
    #pragma unroll
    for (int nt = 0; nt < NT; nt++) bu[nt] = B4[(wn0 + nt * 8 + g) * 5 + q];
    #pragma unroll
    for (int mt = 0; mt < 2; mt++)
        #pragma unroll
        for (int nt = 0; nt < NT; nt++)
            mma16(c[mt][nt], aL[mt].x, aH[mt].x, aL[mt].y, aH[mt].y,
                  bu[nt].x, bu[nt].y);
    #pragma unroll
    for (int mt = 0; mt < 2; mt++)
        #pragma unroll
        for (int nt = 0; nt < NT; nt++)
            mma16(c[mt][nt], aL[mt].z, aH[mt].z, aL[mt].w, aH[mt].w,
                  bu[nt].z, bu[nt].w);
}

// ---------------- merged one-time prep (all weight converts + h zero) ----------
__device__ __forceinline__ void conv_one(
    const float* __restrict__ in, uint32_t* __restrict__ out,
    int idx, int R, int Rout, int K)
{
    const int kc  = idx / (Rout * 16);
    const int rem = idx % (Rout * 16);
    const int r = rem >> 4, slot = rem & 15;
    const int kp = (slot & 3) * 4 + (slot >> 2);
    const int k0 = kc * 32 + kp * 2;
    const float v0 = (r < R && k0     < K) ? in[(size_t)r * K + k0]     : 0.f;
    const float v1 = (r < R && k0 + 1 < K) ? in[(size_t)r * K + k0 + 1] : 0.f;
    out[idx] = pkh2(v0, v1);
}

__global__ void prep_all(
    const float* __restrict__ emb,
    const float* __restrict__ wihf, const float* __restrict__ wihb,
    const float* __restrict__ whhf, const float* __restrict__ whhb,
    const float* __restrict__ wl,   const float* __restrict__ wg,
    uint32_t* __restrict__ embt, uint32_t* __restrict__ wiht,
    uint32_t* __restrict__ whht, uint32_t* __restrict__ wlt,
    uint32_t* __restrict__ wgt,  uint32_t* __restrict__ htf)
{
    int idx = blockIdx.x * 256 + threadIdx.x;
    if (idx < S_EMB) { conv_one(emb, embt, idx, VOCAB, VROWS, EMBD); return; }
    idx -= S_EMB;
    if (idx < S_WIH) { conv_one(wihf, wiht, idx, G3, G3, EMBD); return; }
    idx -= S_WIH;
    if (idx < S_WIH) { conv_one(wihb, wiht + S_WIH, idx, G3, G3, EMBD); return; }
    idx -= S_WIH;
    if (idx < S_WHH) { conv_one(whhf, whht, idx, G3, G3, HID); return; }
    idx -= S_WHH;
    if (idx < S_WHH) { conv_one(whhb, whht + S_WHH, idx, G3, G3, HID); return; }
    idx -= S_WHH;
    if (idx < S_WD)  { conv_one(wl, wlt, idx, DD, DD, DD); return; }
    idx -= S_WD;
    if (idx < S_WD)  { conv_one(wg, wgt, idx, DD, DD, DD); return; }
    idx -= S_WD;
    if (idx < S_HTF) htf[idx] = 0u;
}

// -------- merged y prep: fp16x2 permuted convert + masked max pool --------------
// thread = (b, kc, j): loops 15 timesteps, writes ywh rows and ypool maxima
__global__ void yprep(const int* __restrict__ inds,
                      const float* __restrict__ yw,
                      uint32_t* __restrict__ ywh,
                      float* __restrict__ ypool)
{
    const int u = blockIdx.x * 256 + threadIdx.x;   // BATCH*32*4 units
    if (u >= BATCH * 128) return;
    const int b   = u >> 7;
    const int rem = u & 127;
    const int kc  = rem >> 2, j = rem & 3;

    float mx[8];
    #pragma unroll
    for (int i = 0; i < 8; i++) mx[i] = -INFINITY;

    #pragma unroll
    for (int t = 0; t < TT; t++) {
        const int r = b * TT + t;
        const float* p = yw + (size_t)r * DD + kc * 32 + 2 * j;
        const float2 f0 = *(const float2*)(p);
        const float2 f1 = *(const float2*)(p + 8);
        const float2 f2 = *(const float2*)(p + 16);
        const float2 f3 = *(const float2*)(p + 24);
        uint4 w;
        w.x = pkh2(f0.x, f0.y); w.y = pkh2(f1.x, f1.y);
        w.z = pkh2(f2.x, f2.y); w.w = pkh2(f3.x, f3.y);
        *(uint4*)&ywh[((size_t)kc * BT + r) * 16 + j * 4] = w;
        if (inds[r] != 0) {
            mx[0] = fmaxf(mx[0], f0.x); mx[1] = fmaxf(mx[1], f0.y);
            mx[2] = fmaxf(mx[2], f1.x); mx[3] = fmaxf(mx[3], f1.y);
            mx[4] = fmaxf(mx[4], f2.x); mx[5] = fmaxf(mx[5], f2.y);
            mx[6] = fmaxf(mx[6], f3.x); mx[7] = fmaxf(mx[7], f3.y);
        }
    }
    float* op = ypool + (size_t)b * DD + kc * 32 + 2 * j;
    *(float2*)(op)      = make_float2(mx[0], mx[1]);
    *(float2*)(op + 8)  = make_float2(mx[2], mx[3]);
    *(float2*)(op + 16) = make_float2(mx[4], mx[5]);
    *(float2*)(op + 24) = make_float2(mx[6], mx[7]);
}

// ================= git GEMM: prepped x prepped, 3-stage cp.async ===============
__global__ void __launch_bounds__(256) hgemm_pp(
    const uint32_t* __restrict__ At,
    const uint32_t* __restrict__ Wt, const uint32_t* __restrict__ Wt2,
    const float* __restrict__ bias, const float* __restrict__ bias2,
    float* __restrict__ C, float* __restrict__ C2,
    int Mout, int Ar, int N, int KC)
{
    const uint32_t* W = Wt; const float* bi = bias; float* Co = C;
    if (blockIdx.z == 1) { W = Wt2; bi = bias2; Co = C2; }
    extern __shared__ uint32_t sm[];
    const uint32_t sbase = (uint32_t)__cvta_generic_to_shared(sm);

    const int tid  = threadIdx.x;
    const int lane = tid & 31, wid = tid >> 5;
    const int g = lane >> 2, q = lane & 3;
    const int wm0 = (wid & 3) * 32;
    const int wn0 = (wid >> 2) * 64;
    const int row0 = blockIdx.x * 128;
    const int col0 = blockIdx.y * 128;

    auto issue = [&](int kc, int st) {
        const uint32_t s0 = sbase + st * GP_STAGE * 4;
        #pragma unroll
        for (int s = 0; s < 2; s++) {
            const int u = tid + s * 256;
            const int r = u >> 2, j = u & 3;
            cp16(s0 + (r * KROW + j * 4) * 4,
                 At + ((size_t)kc * Ar + row0 + r) * 16 + j * 4);
        }
        #pragma unroll
        for (int s = 0; s < 2; s++) {
            const int u = tid + s * 256;
            const int r = u >> 2, j = u & 3;
            cp16(s0 + (128 * KROW + r * KROW + j * 4) * 4,
                 W + ((size_t)kc * N + col0 + r) * 16 + j * 4);
        }
        asm volatile("cp.async.commit_group;");
    };

    float c[2][8][4];
    #pragma unroll
    for (int mt = 0; mt < 2; mt++)
        #pragma unroll
        for (int nt = 0; nt < 8; nt++)
            #pragma unroll
            for (int j = 0; j < 4; j++) c[mt][nt][j] = 0.f;

    issue(0, 0);
    if (KC > 1) issue(1, 1);
    for (int it = 0; it < KC; it++) {
        if (it + 1 < KC) asm volatile("cp.async.wait_group 1;");
        else             asm volatile("cp.async.wait_group 0;");
        __syncthreads();
        if (it + 2 < KC) issue(it + 2, (it + 2) % 3);
        const uint32_t* curS = sm + (it % 3) * GP_STAGE;
        mm16t<8>(curS, curS + 128 * KROW, wm0, wn0, g, q, c);
        __syncthreads();
    }

    #pragma unroll
    for (int mt = 0; mt < 2; mt++) {
        const int r = row0 + wm0 + mt * 16 + g;
        #pragma unroll
        for (int nt = 0; nt < 8; nt++) {
            const int n = col0 + wn0 + nt * 8 + q * 2;
            const float b0 = bi[n], b1 = bi[n + 1];
            if (r < Mout)
                *(float2*)(Co + (size_t)r * N + n) =
                    make_float2(c[mt][nt][0] + b0, c[mt][nt][1] + b1);
            if (r + 8 < Mout)
                *(float2*)(Co + (size_t)(r + 8) * N + n) =
                    make_float2(c[mt][nt][2] + b0, c[mt][nt][3] + b1);
        }
    }
}

// ================= fused GRU recurrence step (fp16, cp.async) ==================
__global__ void __launch_bounds__(256, 2) rec_step(
    const int* __restrict__ inds,
    const float* __restrict__ git_f, const float* __restrict__ git_b,
    const uint32_t* __restrict__ whht,
    const float* __restrict__ bhh_f, const float* __restrict__ bhh_b,
    uint32_t* __restrict__ htf,
    float* __restrict__ y_word, int t)
{
    const int dir = blockIdx.z;
    const int cur = t & 1, nxt = cur ^ 1;
    const float* git = dir ? git_b : git_f;
    const float* bhh = dir ? bhh_b : bhh_f;
    const int tt  = dir ? (TT - 1 - t) : t;
    const int off = dir ? HID : 0;
    const uint32_t* Wp    = whht + (size_t)dir * S_WHH;
    const uint32_t* hprev = htf + ((size_t)dir * 2 + cur) * BATCH * 256;
    uint32_t*       hnext = htf + ((size_t)dir * 2 + nxt) * BATCH * 256;

    extern __shared__ uint32_t sm[];
    const uint32_t sbase = (uint32_t)__cvta_generic_to_shared(sm);

    const int tid  = threadIdx.x;
    const int lane = tid & 31, wid = tid >> 5;
    const int g = lane >> 2, q = lane & 3;
    const int wm0 = (wid & 1) * 32;       // 2 m-warps
    const int wn0 = (wid >> 1) * 16;      // 4 n-warps (16 hid cols each)
    const int row0 = blockIdx.x * 64;
    const int col0 = blockIdx.y * 64;

    auto issue = [&](int kc, int st) {
        const uint32_t s0 = sbase + st * RC_STAGE * 4;
        {   // A: 64 rows x 4 units = 256
            const int r = tid >> 2, j = tid & 3;
            cp16(s0 + (r * KROW + j * 4) * 4,
                 hprev + (size_t)(row0 + r) * 256 + kc * 16 + j * 4);
        }
        #pragma unroll
        for (int s = 0; s < 3; s++) {     // B: 192 rows x 4 units = 768
            const int u = tid + s * 256;
            const int r = u >> 2, j = u & 3;
            const int gate = r >> 6, wi = r & 63;
            cp16(s0 + (64 * KROW + r * KROW + j * 4) * 4,
                 Wp + ((size_t)kc * G3 + gate * HID + col0 + wi) * 16 + j * 4);
        }
        asm volatile("cp.async.commit_group;");
    };

    float c[3][2][2][4];
    #pragma unroll
    for (int gt = 0; gt < 3; gt++)
        #pragma unroll
        for (int mt = 0; mt < 2; mt++)
            #pragma unroll
            for (int nt = 0; nt < 2; nt++)
                #pragma unroll
                for (int j = 0; j < 4; j++) c[gt][mt][nt][j] = 0.f;

    const int nk = HID / 32;  // 16
    issue(0, 0);
    issue(1, 1);

    for (int it = 0; it < nk; it++) {
        if (it + 1 < nk) asm volatile("cp.async.wait_group 1;");
        else             asm volatile("cp.async.wait_group 0;");
        __syncthreads();
        if (it + 2 < nk) issue(it + 2, (it + 2) % 3);

        const uint32_t* curS = sm + (it % 3) * RC_STAGE;
        const uint4* A4 = (const uint4*)curS;
        const uint4* B4 = (const uint4*)(curS + 64 * KROW);
        const uint4 aL0 = A4[(wm0 + g     ) * 5 + q];
        const uint4 aH0 = A4[(wm0 + g +  8) * 5 + q];
        const uint4 aL1 = A4[(wm0 + g + 16) * 5 + q];
        const uint4 aH1 = A4[(wm0 + g + 24) * 5 + q];
        uint4 bu[3][2];
        #pragma unroll
        for (int gt = 0; gt < 3; gt++)
            #pragma unroll
            for (int nt = 0; nt < 2; nt++)
                bu[gt][nt] = B4[(gt * 64 + wn0 + nt * 8 + g) * 5 + q];
        #pragma unroll
        for (int gt = 0; gt < 3; gt++)
            #pragma unroll
            for (int nt = 0; nt < 2; nt++) {
                mma16(c[gt][0][nt], aL0.x, aH0.x, aL0.y, aH0.y,
                      bu[gt][nt].x, bu[gt][nt].y);
                mma16(c[gt][1][nt], aL1.x, aH1.x, aL1.y, aH1.y,
                      bu[gt][nt].x, bu[gt][nt].y);
            }
        #pragma unroll
        for (int gt = 0; gt < 3; gt++)
            #pragma unroll
            for (int nt = 0; nt < 2; nt++) {
                mma16(c[gt][0][nt], aL0.z, aH0.z, aL0.w, aH0.w,
                      bu[gt][nt].z, bu[gt][nt].w);
                mma16(c[gt][1][nt], aL1.z, aH1.z, aL1.w, aH1.w,
                      bu[gt][nt].z, bu[gt][nt].w);
            }
        __syncthreads();
    }

    // ---- GRU cell epilogue ----
    #pragma unroll
    for (int mt = 0; mt < 2; mt++) {
        #pragma unroll
        for (int rr = 0; rr < 2; rr++) {
            const int b = row0 + wm0 + mt * 16 + g + rr * 8;
            const int tok = inds[b * TT + tt];
            const float* gib = git + (size_t)tok * G3;
            #pragma unroll
            for (int nt = 0; nt < 2; nt++) {
                const int hg = col0 + wn0 + nt * 8 + q * 2;   // even
                const int j0 = rr * 2;
                const int kpair = (hg & 31) >> 1;
                const int slot = (kpair & 3) * 4 + (kpair >> 2);
                const size_t hw = (size_t)b * 256 + (hg >> 5) * 16 + slot;
                const __half2 hp2 = *(const __half2*)&hprev[hw];
                float hn2[2];
                #pragma unroll
                for (int e = 0; e < 2; e++) {
                    const int hh = hg + e;
                    const float gir = gib[hh];
                    const float giz = gib[HID + hh];
                    const float gin = gib[2 * HID + hh];
                    const float ghr = c[0][mt][nt][j0 + e] + bhh[hh];
                    const float ghz = c[1][mt][nt][j0 + e] + bhh[HID + hh];
                    const float ghn = c[2][mt][nt][j0 + e] + bhh[2 * HID + hh];
                    const float hp = (e == 0) ? __low2float(hp2) : __high2float(hp2);
                    const float r = sigm(gir + ghr);
                    const float z = sigm(giz + ghz);
                    const float n = tanhf(gin + r * ghn);
                    hn2[e] = (1.f - z) * n + z * hp;
                }
                hnext[hw] = pkh2(hn2[0], hn2[1]);
                *(float2*)(y_word + (size_t)(b * TT + tt) * DD + off + hg) =
                    make_float2(hn2[0], hn2[1]);
            }
        }
    }
}

// ================= gw GEMM: fp32-A convert x prepped-B =========================
__global__ void __launch_bounds__(256) hgemm_gw(
    const float* __restrict__ A, const uint32_t* __restrict__ Wt,
    const float* __restrict__ bias, const float* __restrict__ wc,
    float* __restrict__ C)
{
    extern __shared__ uint32_t sm[];
    const int tid  = threadIdx.x;
    const int lane = tid & 31, wid = tid >> 5;
    const int g = lane >> 2, q = lane & 3;
    const int wm0 = (wid & 3) * 32;
    const int wn0 = (wid >> 2) * 64;
    const int row0 = blockIdx.x * 128;
    const int col0 = blockIdx.y * 128;
    const int sr = tid >> 1;
    const int j0s = (tid & 1) * 2;

    const float* arow = A + (size_t)(row0 + sr) * DD;

    auto stageA = [&](uint32_t* sa, int kc) {
        #pragma unroll
        for (int jj = 0; jj < 2; jj++) {
            const int j = j0s + jj;
            const float* p = arow + kc * 32 + 2 * j;
            const float2 f0 = *(const float2*)(p);
            const float2 f1 = *(const float2*)(p + 8);
            const float2 f2 = *(const float2*)(p + 16);
            const float2 f3 = *(const float2*)(p + 24);
            uint4 w;
            w.x = pkh2(f0.x, f0.y); w.y = pkh2(f1.x, f1.y);
            w.z = pkh2(f2.x, f2.y); w.w = pkh2(f3.x, f3.y);
            *(uint4*)&sa[sr * KROW + j * 4] = w;
        }
    };
    auto stageB = [&](uint32_t* sb, const uint4* rbu) {
        #pragma unroll
        for (int jj = 0; jj < 2; jj++)
            *(uint4*)&sb[sr * KROW + (j0s + jj) * 4] = rbu[jj];
    };
    auto loadB = [&](uint4* rbu, int kc) {
        #pragma unroll
        for (int jj = 0; jj < 2; jj++)
            rbu[jj] = *(const uint4*)(Wt + ((size_t)kc * DD + col0 + sr) * 16
                                          + (j0s + jj) * 4);
    };

    float c[2][8][4];
    #pragma unroll
    for (int mt = 0; mt < 2; mt++)
        #pragma unroll
        for (int nt = 0; nt < 8; nt++)
            #pragma unroll
            for (int j = 0; j < 4; j++) c[mt][nt][j] = 0.f;

    const int nk = DD / 32;
    uint4 rbu[2];
    loadB(rbu, 0);
    stageA(sm, 0);
    stageB(sm + 128 * KROW, rbu);
    __syncthreads();

    for (int it = 0; it < nk; it++) {
        const bool more = (it + 1 < nk);
        if (more) loadB(rbu, it + 1);
        const uint32_t* curS = sm + (it & 1) * GW_STAGE;
        mm16t<8>(curS, curS + 128 * KROW, wm0, wn0, g, q, c);
        if (more) {
            uint32_t* nx = sm + ((it + 1) & 1) * GW_STAGE;
            stageA(nx, it + 1);
            stageB(nx + 128 * KROW, rbu);
            __syncthreads();
        }
    }

    #pragma unroll
    for (int mt = 0; mt < 2; mt++) {
        const int r = row0 + wm0 + mt * 16 + g;
        #pragma unroll
        for (int nt = 0; nt < 8; nt++) {
            const int n = col0 + wn0 + nt * 8 + q * 2;
            const float b0 = bias[n], b1 = bias[n + 1];
            const float w0 = wc[n], w1 = wc[n + 1];
            *(float2*)(C + (size_t)r * DD + n) =
                make_float2(tanhf(c[mt][nt][0] + b0) * w0,
                            tanhf(c[mt][nt][1] + b1) * w1);
            *(float2*)(C + (size_t)(r + 8) * DD + n) =
                make_float2(tanhf(c[mt][nt][2] + b0) * w0,
                            tanhf(c[mt][nt][3] + b1) * w1);
        }
    }
}

// ================= fused attention logits: 512t, all cp.async, 3 stages ========
__global__ void __launch_bounds__(512) attn_w(
    const uint32_t* __restrict__ ywh, const uint32_t* __restrict__ wlt,
    const float* __restrict__ bl, const float* __restrict__ gw,
    const float* __restrict__ bc, float* __restrict__ wraw)
{
    extern __shared__ uint32_t sm[];
    __shared__ float red[128][17];

    const int tid  = threadIdx.x;
    const int lane = tid & 31, wid = tid >> 5;       // 0..15
    const int g = lane >> 2, q = lane & 3;
    const int wm0 = (wid & 3) * 32;
    const int wn0 = (wid >> 2) * 64;
    const int row0 = blockIdx.x * 128;
    const uint32_t sbase = (uint32_t)__cvta_generic_to_shared(sm);

    auto issue = [&](int kc, int col0, int st) {
        const uint32_t s0 = sbase + st * AT_STAGE * 4;
        {   // A: 128 rows x 4 units = 512
            const int r = tid >> 2, j = tid & 3;
            cp16(s0 + (r * KROW + j * 4) * 4,
                 ywh + ((size_t)kc * BT + row0 + r) * 16 + j * 4);
        }
        {   // B: 256 rows x 4 units = 1024 (units tid, tid+512)
            const int r = tid >> 2, j = tid & 3;
            cp16(s0 + (128 * KROW + r * KROW + j * 4) * 4,
                 wlt + ((size_t)kc * DD + col0 + r) * 16 + j * 4);
            const int u = tid + 512;
            const int r2 = u >> 2, j2 = u & 3;
            cp16(s0 + (128 * KROW + r2 * KROW + j2 * 4) * 4,
                 wlt + ((size_t)kc * DD + col0 + r2) * 16 + j2 * 4);
        }
        asm volatile("cp.async.commit_group;");
    };

    int rbi0[2], rbi1[2];
    #pragma unroll
    for (int mt = 0; mt < 2; mt++) {
        const int r = row0 + wm0 + mt * 16 + g;
        rbi0[mt] = r / TT;
        rbi1[mt] = (r + 8) / TT;
    }
    float rowsum[2][2] = {{0.f, 0.f}, {0.f, 0.f}};

    const int nk = DD / 32;   // 32

    for (int ct = 0; ct < DD / 256; ct++) {
        const int col0 = ct * 256;

        float c[2][8][4];
        #pragma unroll
        for (int mt = 0; mt < 2; mt++)
            #pragma unroll
            for (int nt = 0; nt < 8; nt++)
                #pragma unroll
                for (int j = 0; j < 4; j++) c[mt][nt][j] = 0.f;

        issue(0, col0, 0);
        issue(1, col0, 1);

        for (int it = 0; it < nk; it++) {
            if (it + 1 < nk) asm volatile("cp.async.wait_group 1;");
            else             asm volatile("cp.async.wait_group 0;");
            __syncthreads();
            if (it + 2 < nk) issue(it + 2, col0, (it + 2) % 3);
            const uint32_t* curS = sm + (it % 3) * AT_STAGE;
            mm16t<8>(curS, curS + 128 * KROW, wm0, wn0, g, q, c);
            __syncthreads();
        }

        #pragma unroll
        for (int mt = 0; mt < 2; mt++) {
            #pragma unroll
            for (int nt = 0; nt < 8; nt++) {
                const int n = col0 + wn0 + nt * 8 + q * 2;
                const float bb0 = bl[n], bb1 = bl[n + 1];
                rowsum[mt][0] += tanhf(c[mt][nt][0] + bb0) * gw[(size_t)rbi0[mt] * DD + n]
                               + tanhf(c[mt][nt][1] + bb1) * gw[(size_t)rbi0[mt] * DD + n + 1];
                rowsum[mt][1] += tanhf(c[mt][nt][2] + bb0) * gw[(size_t)rbi1[mt] * DD + n]
                               + tanhf(c[mt][nt][3] + bb1) * gw[(size_t)rbi1[mt] * DD + n + 1];
            }
        }
    }

    const int rc = (wid >> 2) * 4 + q;   // 0..15
    #pragma unroll
    for (int mt = 0; mt < 2; mt++) {
        red[wm0 + mt * 16 + g    ][rc] = rowsum[mt][0];
        red[wm0 + mt * 16 + g + 8][rc] = rowsum[mt][1];
    }
    __syncthreads();
    if (tid < 128) {
        float s = 0.f;
        #pragma unroll
        for (int x = 0; x < 16; x++) s += red[tid][x];
        wraw[row0 + tid] = s + bc[0];
    }
}

// ---------------- softmax over T + weighted sum -> output ----------------------
__global__ void softmax_out(const float* __restrict__ w_raw,
                            const float* __restrict__ y_word,
                            float* __restrict__ out)
{
    __shared__ float p[TT];
    const int b = blockIdx.x;
    if (threadIdx.x == 0) {
        float v[TT]; float mx = -INFINITY;
        #pragma unroll
        for (int t = 0; t < TT; t++) { v[t] = w_raw[b * TT + t]; mx = fmaxf(mx, v[t]); }
        float s = 0.f;
        #pragma unroll
        for (int t = 0; t < TT; t++) { v[t] = expf(v[t] - mx); s += v[t]; }
        const float inv = 1.f / s;
        #pragma unroll
        for (int t = 0; t < TT; t++) p[t] = v[t] * inv;
    }
    __syncthreads();
    for (int d = threadIdx.x; d < DD; d += 256) {
        float s = 0.f;
        #pragma unroll
        for (int t = 0; t < TT; t++)
            s += p[t] * y_word[((size_t)(b * TT + t)) * DD + d];
        out[(size_t)b * DD + d] = s;
    }
}

// ---------------- host launch --------------------------------------------------
extern "C" void kernel_launch(void* const* d_in, const int* in_sizes, int n_in,
                              void* d_out, int out_size)
{
    const int*   inds     = (const int*)  d_in[0];
    const float* emb      = (const float*)d_in[1];
    const float* w_ih_f   = (const float*)d_in[2];
    const float* w_hh_f   = (const float*)d_in[3];
    const float* b_ih_f   = (const float*)d_in[4];
    const float* b_hh_f   = (const float*)d_in[5];
    const float* w_ih_b   = (const float*)d_in[6];
    const float* w_hh_b   = (const float*)d_in[7];
    const float* b_ih_b   = (const float*)d_in[8];
    const float* b_hh_b   = (const float*)d_in[9];
    const float* w_local  = (const float*)d_in[10];
    const float* b_local  = (const float*)d_in[11];
    const float* w_global = (const float*)d_in[12];
    const float* b_global = (const float*)d_in[13];
    const float* w_common = (const float*)d_in[14];
    const float* b_common = (const float*)d_in[15];
    float* out = (float*)d_out;

    float *git_f, *git_b, *yw, *yp, *gw, *wraw;
    uint32_t *embt, *wiht, *whht, *wlt, *wgt, *htf, *ywh;
    cudaGetSymbolAddress((void**)&git_f, g_git_f);
    cudaGetSymbolAddress((void**)&git_b, g_git_b);
    cudaGetSymbolAddress((void**)&embt, g_embt);
    cudaGetSymbolAddress((void**)&wiht, g_wiht);
    cudaGetSymbolAddress((void**)&whht, g_whht);
    cudaGetSymbolAddress((void**)&wlt,  g_wlt);
    cudaGetSymbolAddress((void**)&wgt,  g_wgt);
    cudaGetSymbolAddress((void**)&htf,  g_htf);
    cudaGetSymbolAddress((void**)&yw,   g_yword);
    cudaGetSymbolAddress((void**)&ywh,  g_ywh);
    cudaGetSymbolAddress((void**)&yp,   g_ypool);
    cudaGetSymbolAddress((void**)&gw,   g_gw);
    cudaGetSymbolAddress((void**)&wraw, g_wraw);

    cudaFuncSetAttribute(hgemm_pp, cudaFuncAttributeMaxDynamicSharedMemorySize, GP_SMEM);
    cudaFuncSetAttribute(rec_step, cudaFuncAttributeMaxDynamicSharedMemorySize, RC_SMEM);
    cudaFuncSetAttribute(hgemm_gw, cudaFuncAttributeMaxDynamicSharedMemorySize, GW_SMEM);
    cudaFuncSetAttribute(attn_w,   cudaFuncAttributeMaxDynamicSharedMemorySize, AT_SMEM);

    // 0. merged one-time prep: all weight converts + h zero (single launch)
    prep_all<<<(S_TOTAL + 255) / 256, 256>>>(emb, w_ih_f, w_ih_b, w_hh_f, w_hh_b,
                                             w_local, w_global,
                                             embt, wiht, whht, wlt, wgt, htf);

    // 1. per-vocab gi table (incl. b_ih), both dirs
    dim3 gt_grid(VROWS / 128, G3 / 128, 2);
    hgemm_pp<<<gt_grid, 256, GP_SMEM>>>(embt, wiht, wiht + (size_t)S_WIH,
                                        b_ih_f, b_ih_b, git_f, git_b,
                                        VOCAB, VROWS, G3, 10);

    // 2. fused bidirectional GRU recurrence (64x64, 2 CTAs/SM)
    dim3 rec_grid(BATCH / 64, HID / 64, 2);
    for (int t = 0; t < TT; t++) {
        rec_step<<<rec_grid, 256, RC_SMEM>>>(inds, git_f, git_b, whht,
                                             b_hh_f, b_hh_b, htf, yw, t);
    }

    // 3. merged y prep: fp16x2 permuted convert + masked max pool (one y read)
    yprep<<<(BATCH * 128 + 255) / 256, 256>>>(inds, yw, ywh, yp);

    // 4. gw = tanh(y_pool @ w_global^T + b_global) * w_common
    dim3 gw_grid(BATCH / 128, DD / 128, 1);
    hgemm_gw<<<gw_grid, 256, GW_SMEM>>>(yp, wgt, b_global, w_common, gw);

    // 5. fused l_emb -> tanh -> dot(gw) -> attention logits (all cp.async)
    attn_w<<<BT / 128, 512, AT_SMEM>>>(ywh, wlt, b_local, gw, b_common, wraw);

    // 6. softmax over T + weighted sum
    softmax_out<<<BATCH, 256>>>(wraw, yw, out);
}